// round 14
// baseline (speedup 1.0000x reference)
#include <cuda_runtime.h>
#include <cuda_bf16.h>
#include <cstdint>
#include <math.h>

#define BATCH  4
#define SEQ    2048
#define DMODEL 1024
#define DK     64

// projected activations: Q split bf16; K single rn-bf16
__device__ __align__(16) __nv_bfloat16 g_qh[BATCH * SEQ * DK];
__device__ __align__(16) __nv_bfloat16 g_ql[BATCH * SEQ * DK];
__device__ __align__(16) __nv_bfloat16 g_kh[BATCH * SEQ * DK];
// V transposed: [batch][vcol][seq], split
__device__ __align__(16) __nv_bfloat16 g_vth[BATCH * DK * SEQ];
__device__ __align__(16) __nv_bfloat16 g_vtl[BATCH * DK * SEQ];
// pre-transposed + bf16-split weights: [matrix][n][k]
__device__ __align__(16) __nv_bfloat16 g_wt_hi[3 * DK * DMODEL];
__device__ __align__(16) __nv_bfloat16 g_wt_lo[3 * DK * DMODEL];
// kv-split partials: unnormalized numerators + denominators (linear merge)
__device__ __align__(16) float g_pO[2 * BATCH * SEQ * DK];
__device__ __align__(16) float g_pl[2 * BATCH * SEQ];

// ============================ PTX helpers ============================
__device__ __forceinline__ uint32_t smem_u32(const void* p) {
    uint32_t a;
    asm("{ .reg .u64 t; cvta.to.shared.u64 t, %1; cvt.u32.u64 %0, t; }"
        : "=r"(a) : "l"(p));
    return a;
}
__device__ __forceinline__ void mma16816s(float c[4], uint32_t a0, uint32_t a1,
                                          uint32_t a2, uint32_t a3,
                                          uint32_t b0, uint32_t b1) {
    asm volatile(
        "mma.sync.aligned.m16n8k16.row.col.f32.bf16.bf16.f32 "
        "{%0, %1, %2, %3}, {%4, %5, %6, %7}, {%8, %9}, {%0, %1, %2, %3};"
        : "+f"(c[0]), "+f"(c[1]), "+f"(c[2]), "+f"(c[3])
        : "r"(a0), "r"(a1), "r"(a2), "r"(a3), "r"(b0), "r"(b1));
}
#define LDSM_X4(r0, r1, r2, r3, addr) \
    asm volatile("ldmatrix.sync.aligned.m8n8.x4.shared.b16 {%0,%1,%2,%3}, [%4];" \
        : "=r"(r0), "=r"(r1), "=r"(r2), "=r"(r3) : "r"(addr))
#define CP_ASYNC16(dst, src) \
    asm volatile("cp.async.cg.shared.global [%0], [%1], 16;" \
        :: "r"(dst), "l"(src) : "memory")
#define CP_COMMIT() asm volatile("cp.async.commit_group;" ::: "memory")
#define CP_WAIT0()  asm volatile("cp.async.wait_group 0;" ::: "memory")
#define CP_WAIT1()  asm volatile("cp.async.wait_group 1;" ::: "memory")

// Fast Dekker split: hi = truncate-to-bf16 (exact residual), lo = rn(residual).
__device__ __forceinline__ void fsplit2(float a, float b, uint32_t& hi, uint32_t& lo) {
    uint32_t ua = __float_as_uint(a), ub = __float_as_uint(b);
    hi = __byte_perm(ua, ub, 0x7632);
    float ra = a - __uint_as_float(ua & 0xffff0000u);
    float rb = b - __uint_as_float(ub & 0xffff0000u);
    __nv_bfloat162 l2 = __floats2bfloat162_rn(ra, rb);
    lo = *reinterpret_cast<uint32_t*>(&l2);
}
// round-to-nearest bf16x2 pack
__device__ __forceinline__ uint32_t frn2(float a, float b) {
    __nv_bfloat162 r2 = __floats2bfloat162_rn(a, b);
    return *reinterpret_cast<uint32_t*>(&r2);
}

// ============================ prep: transpose + split weights ============================
__global__ __launch_bounds__(256) void prep_w(const float* __restrict__ Wq,
                                              const float* __restrict__ Wk,
                                              const float* __restrict__ Wv)
{
    const int m = blockIdx.x;
    const float* W = (m == 0) ? Wq : (m == 1) ? Wk : Wv;   // [1024, 64] row-major
    __nv_bfloat16* th = g_wt_hi + m * DK * DMODEL;
    __nv_bfloat16* tl = g_wt_lo + m * DK * DMODEL;
    const int tid = threadIdx.x;
    const int k0 = blockIdx.y * 16;
    const int n = tid >> 2, kq = tid & 3;

    float v[4];
    #pragma unroll
    for (int e = 0; e < 4; e++)
        v[e] = __ldg(W + (size_t)(k0 + kq * 4 + e) * 64 + n);

    uint32_t h[2], l[2];
    #pragma unroll
    for (int e = 0; e < 2; e++) {
        float a = v[2 * e], b = v[2 * e + 1];
        uint32_t ua = __float_as_uint(a), ub = __float_as_uint(b);
        h[e] = __byte_perm(ua, ub, 0x7632);
        float ra = a - __uint_as_float(ua & 0xffff0000u);
        float rb = b - __uint_as_float(ub & 0xffff0000u);
        l[e] = frn2(ra, rb);
    }
    size_t off = (size_t)n * DMODEL + k0 + kq * 4;
    *(uint2*)&th[off] = make_uint2(h[0], h[1]);
    *(uint2*)&tl[off] = make_uint2(l[0], l[1]);
}

// ============================ mma.sync projection ============================
// X loaded directly as register A-fragments (no X smem round-trip).
// W: 3-buffer cp.async pipeline in smem; one syncthreads per iteration.
#define WSTR 72
static const int WBUF_E = 2 * 64 * WSTR;           // hi+lo per buffer = 9216 elems
static const int WBUF_B = WBUF_E * 2;              // 18432 B
static const int PROJ_SMEM = 3 * WBUF_B;           // 55296 B (>= V stage 33792 B)

__global__ __launch_bounds__(256, 2) void proj_mma(
    const float* __restrict__ Xq, const float* __restrict__ Xk,
    const float* __restrict__ Xv,
    const float* __restrict__ bq, const float* __restrict__ bk,
    const float* __restrict__ bv)
{
    extern __shared__ __nv_bfloat16 sm[];

    const int tid = threadIdx.x;
    const int wid = tid >> 5;
    const int lane = tid & 31;
    const int g  = lane >> 2;
    const int tg = lane & 3;
    const int m = blockIdx.y;
    const int row0 = blockIdx.x * 128;
    const int wrow = wid * 16;

    const float* X    = (m == 0) ? Xq : (m == 1) ? Xk : Xv;
    const float* bias = (m == 0) ? bq : (m == 1) ? bk : bv;
    const __nv_bfloat16* wh = g_wt_hi + m * DK * DMODEL;
    const __nv_bfloat16* wl = g_wt_lo + m * DK * DMODEL;

    float acc[8][4];
    #pragma unroll
    for (int j = 0; j < 8; j++)
        #pragma unroll
        for (int q = 0; q < 4; q++) acc[j][q] = 0.0f;

    const uint32_t sb = smem_u32(sm);

    // W cp.async thread destinations (buffer-relative)
    const int wn0 = tid >> 3, wc0 = (tid & 7) * 8;
    const int wn1 = (tid + 256) >> 3, wc1 = ((tid + 256) & 7) * 8;
    const uint32_t wd0 = (uint32_t)((wn0 * WSTR + wc0) * 2);
    const uint32_t wd1 = (uint32_t)((wn1 * WSTR + wc1) * 2);
    const uint32_t wlofs = (uint32_t)(64 * WSTR * 2);   // lo-array offset in buffer

    // W ldmatrix lane offset (buffer-relative)
    const int brow = (lane & 7) + ((lane >> 4) & 1) * 8;
    const uint32_t wlm = (uint32_t)((brow * WSTR + ((lane >> 3) & 1) * 8) * 2);

    // X fragment gmem base
    const float* xb = X + (size_t)(row0 + wrow + g) * DMODEL + tg * 2;

    float2 xf[4][4];
    #pragma unroll
    for (int ks = 0; ks < 4; ks++) {
        const float* p = xb + ks * 16;
        xf[ks][0] = *(const float2*)(p);
        xf[ks][1] = *(const float2*)(p + 8 * DMODEL);
        xf[ks][2] = *(const float2*)(p + 8);
        xf[ks][3] = *(const float2*)(p + 8 * DMODEL + 8);
    }

    auto stage_w = [&](int b, int c) {
        const uint32_t base = sb + (uint32_t)(b * WBUF_B);
        const int co = c * 64;
        CP_ASYNC16(base + wd0,         wh + wn0 * DMODEL + co + wc0);
        CP_ASYNC16(base + wd0 + wlofs, wl + wn0 * DMODEL + co + wc0);
        CP_ASYNC16(base + wd1,         wh + wn1 * DMODEL + co + wc1);
        CP_ASYNC16(base + wd1 + wlofs, wl + wn1 * DMODEL + co + wc1);
        CP_COMMIT();
    };
    stage_w(0, 0);
    stage_w(1, 1);

    for (int c = 0; c < 16; c++) {
        if (c < 15) { CP_WAIT1(); } else { CP_WAIT0(); }
        __syncthreads();
        if (c < 14) stage_w((c + 2) % 3, c + 2);

        const uint32_t whb = sb + (uint32_t)((c % 3) * WBUF_B) + wlm;
        const uint32_t wlb = whb + wlofs;

        #pragma unroll
        for (int ks = 0; ks < 4; ks++) {
            uint32_t ah0, ah1, ah2, ah3, al0, al1, al2, al3;
            fsplit2(xf[ks][0].x, xf[ks][0].y, ah0, al0);
            fsplit2(xf[ks][1].x, xf[ks][1].y, ah1, al1);
            fsplit2(xf[ks][2].x, xf[ks][2].y, ah2, al2);
            fsplit2(xf[ks][3].x, xf[ks][3].y, ah3, al3);
            #pragma unroll
            for (int t = 0; t < 4; t++) {
                const uint32_t toff = t * (16 * WSTR * 2) + ks * 32;
                uint32_t bh0, bh1, bh2, bh3, bl0, bl1, bl2, bl3;
                LDSM_X4(bh0, bh1, bh2, bh3, whb + toff);
                LDSM_X4(bl0, bl1, bl2, bl3, wlb + toff);
                mma16816s(acc[2*t],   ah0, ah1, ah2, ah3, bh0, bh1);
                mma16816s(acc[2*t],   ah0, ah1, ah2, ah3, bl0, bl1);
                mma16816s(acc[2*t],   al0, al1, al2, al3, bh0, bh1);
                mma16816s(acc[2*t+1], ah0, ah1, ah2, ah3, bh2, bh3);
                mma16816s(acc[2*t+1], ah0, ah1, ah2, ah3, bl2, bl3);
                mma16816s(acc[2*t+1], al0, al1, al2, al3, bh2, bh3);
            }
        }

        if (c < 15) {
            const float* xc = xb + (c + 1) * 64;
            #pragma unroll
            for (int ks = 0; ks < 4; ks++) {
                const float* p = xc + ks * 16;
                xf[ks][0] = *(const float2*)(p);
                xf[ks][1] = *(const float2*)(p + 8 * DMODEL);
                xf[ks][2] = *(const float2*)(p + 8);
                xf[ks][3] = *(const float2*)(p + 8 * DMODEL + 8);
            }
        }
    }

    // ---------------- epilogue ----------------
    if (m == 0) {
        #pragma unroll
        for (int j = 0; j < 8; j++) {
            const int col = j * 8 + tg * 2;
            const float b0 = __ldg(bias + col);
            const float b1 = __ldg(bias + col + 1);
            uint32_t h, l;
            size_t r0 = (size_t)(row0 + wrow + g) * DK + col;
            size_t r1 = (size_t)(row0 + wrow + g + 8) * DK + col;
            fsplit2(acc[j][0] + b0, acc[j][1] + b1, h, l);
            *(uint32_t*)&g_qh[r0] = h; *(uint32_t*)&g_ql[r0] = l;
            fsplit2(acc[j][2] + b0, acc[j][3] + b1, h, l);
            *(uint32_t*)&g_qh[r1] = h; *(uint32_t*)&g_ql[r1] = l;
        }
    } else if (m == 1) {
        #pragma unroll
        for (int j = 0; j < 8; j++) {
            const int col = j * 8 + tg * 2;
            const float b0 = __ldg(bias + col);
            const float b1 = __ldg(bias + col + 1);
            size_t r0 = (size_t)(row0 + wrow + g) * DK + col;
            size_t r1 = (size_t)(row0 + wrow + g + 8) * DK + col;
            *(uint32_t*)&g_kh[r0] = frn2(acc[j][0] + b0, acc[j][1] + b1);
            *(uint32_t*)&g_kh[r1] = frn2(acc[j][2] + b0, acc[j][3] + b1);
        }
    } else {
        __syncthreads();
        float* stage = (float*)sm;    // [128][66] = 33792 B
        #pragma unroll
        for (int j = 0; j < 8; j++) {
            const int col = j * 8 + tg * 2;
            const float b0 = __ldg(bias + col);
            const float b1 = __ldg(bias + col + 1);
            stage[(wrow + g) * 66 + col]         = acc[j][0] + b0;
            stage[(wrow + g) * 66 + col + 1]     = acc[j][1] + b1;
            stage[(wrow + g + 8) * 66 + col]     = acc[j][2] + b0;
            stage[(wrow + g + 8) * 66 + col + 1] = acc[j][3] + b1;
        }
        __syncthreads();
        const int bb   = row0 >> 11;
        const int srow = row0 & 2047;
        const int vc = tid >> 2;
        #pragma unroll
        for (int i = 0; i < 16; i++) {
            int sp = (tid & 3) + i * 4;
            int s0 = sp * 2;
            uint32_t h, l;
            fsplit2(stage[s0 * 66 + vc], stage[(s0 + 1) * 66 + vc], h, l);
            size_t off = ((size_t)bb * DK + vc) * SEQ + srow + s0;
            *(uint32_t*)&g_vth[off] = h;
            *(uint32_t*)&g_vtl[off] = l;
        }
    }
}

// ============================ mma.sync flash attention ============================
// grid (32, 4, 2): 64 queries/CTA, keys split 2-way (z). 8 warps; warps 0-3 even
// tiles of this half-range, 4-7 odd. Double-buffered cp.async (UNCHANGED from the
// R11/R13 winner); 2 CTAs/SM. No-max softmax => partials are LINEAR: CTAs write
// unnormalized O-sums + l-sums; attn_merge does (O0+O1)/(l0+l1).
#define ASTR 72
static const int TILE_E = 64 * ASTR;                 // 4608 elems per tile
static const int ABUF_E = 6 * TILE_E;                // 2 tiles x 3 arrays
static const int AT_BYTES = 2 * ABUF_E * 2;          // 110592 B

__device__ __forceinline__ void attn_stage(int b, int kb0, int buf, uint32_t sb, int tid)
{
    const uint32_t bufb = (uint32_t)(buf * ABUF_E * 2);
    #pragma unroll
    for (int t = 0; t < 2; t++) {
        const int kb = kb0 + t;
        #pragma unroll
        for (int u = 0; u < 2; u++) {
            int idx = tid + u * 256;
            int r = idx >> 3, cq = idx & 7;
            size_t koff = ((size_t)b * SEQ + kb * 64 + r) * DK + cq * 8;
            size_t voff = ((size_t)b * DK + r) * SEQ + kb * 64 + cq * 8;
            uint32_t dst = sb + bufb + (uint32_t)((t * TILE_E + r * ASTR + cq * 8) * 2);
            CP_ASYNC16(dst,                  g_kh + koff);
            CP_ASYNC16(dst + 2 * TILE_E * 2, g_vth + voff);
            CP_ASYNC16(dst + 4 * TILE_E * 2, g_vtl + voff);
        }
    }
}

__global__ __launch_bounds__(256, 2) void attn_mma()
{
    extern __shared__ __nv_bfloat16 asmem[];

    const int b  = blockIdx.y;
    const int q0 = blockIdx.x * 64;
    const int z  = blockIdx.z;
    const int tid = threadIdx.x;
    const int wid = tid >> 5;
    const int lane = tid & 31;
    const int g  = lane >> 2;
    const int tg = lane & 3;
    const int qw = wid & 3;          // query slab
    const int half = wid >> 2;       // key-half (within iteration pair)
    const int wrow = qw * 16;
    const float scale = 0.125f;

    const uint32_t sb = smem_u32(asmem);
    const int brow = (lane & 7) + ((lane >> 4) & 1) * 8;
    const uint32_t lmo = (uint32_t)((brow * ASTR + ((lane >> 3) & 1) * 8) * 2);

    // Q fragments (split)
    const size_t qbase = (size_t)b * SEQ + q0 + wrow;
    uint32_t qh[4][4], ql[4][4];
    #pragma unroll
    for (int ks = 0; ks < 4; ks++) {
        const int c0 = ks * 16 + tg * 2;
        qh[ks][0] = *(const uint32_t*)&g_qh[(qbase + g    ) * DK + c0];
        qh[ks][1] = *(const uint32_t*)&g_qh[(qbase + g + 8) * DK + c0];
        qh[ks][2] = *(const uint32_t*)&g_qh[(qbase + g    ) * DK + c0 + 8];
        qh[ks][3] = *(const uint32_t*)&g_qh[(qbase + g + 8) * DK + c0 + 8];
        ql[ks][0] = *(const uint32_t*)&g_ql[(qbase + g    ) * DK + c0];
        ql[ks][1] = *(const uint32_t*)&g_ql[(qbase + g + 8) * DK + c0];
        ql[ks][2] = *(const uint32_t*)&g_ql[(qbase + g    ) * DK + c0 + 8];
        ql[ks][3] = *(const uint32_t*)&g_ql[(qbase + g + 8) * DK + c0 + 8];
    }

    float l0 = 0.0f, l1 = 0.0f;
    float o[8][4];
    #pragma unroll
    for (int j = 0; j < 8; j++)
        #pragma unroll
        for (int q = 0; q < 4; q++) o[j][q] = 0.0f;

    const int kb_base = z * 16;      // this CTA's 1024-key range = tiles [kb_base, kb_base+16)
    attn_stage(b, kb_base, 0, sb, tid);
    CP_COMMIT();

    for (int it = 0; it < 8; it++) {
        const int bf = it & 1;
        CP_WAIT0();
        __syncthreads();
        if (it < 7) {
            attn_stage(b, kb_base + (it + 1) * 2, bf ^ 1, sb, tid);
            CP_COMMIT();
        }

        const uint32_t kh_a = sb + (uint32_t)(bf * ABUF_E * 2) +
                              (uint32_t)(half * TILE_E * 2) + lmo;
        const uint32_t vh_a = kh_a + 2 * TILE_E * 2;
        const uint32_t vl_a = kh_a + 4 * TILE_E * 2;

        // S = (qh + ql) * K  (2 terms, K single bf16)
        float sc[8][4];
        #pragma unroll
        for (int j = 0; j < 8; j++)
            #pragma unroll
            for (int q = 0; q < 4; q++) sc[j][q] = 0.0f;
        #pragma unroll
        for (int ks = 0; ks < 4; ks++) {
            #pragma unroll
            for (int t = 0; t < 4; t++) {
                const uint32_t toff = t * (16 * ASTR * 2) + ks * 32;
                uint32_t bh0, bh1, bh2, bh3;
                LDSM_X4(bh0, bh1, bh2, bh3, kh_a + toff);
                mma16816s(sc[2*t],   qh[ks][0], qh[ks][1], qh[ks][2], qh[ks][3], bh0, bh1);
                mma16816s(sc[2*t],   ql[ks][0], ql[ks][1], ql[ks][2], ql[ks][3], bh0, bh1);
                mma16816s(sc[2*t+1], qh[ks][0], qh[ks][1], qh[ks][2], qh[ks][3], bh2, bh3);
                mma16816s(sc[2*t+1], ql[ks][0], ql[ks][1], ql[ks][2], ql[ks][3], bh2, bh3);
            }
        }

        // p = exp(s*scale); accumulate l per-lane
        #pragma unroll
        for (int j = 0; j < 8; j++) {
            float p0 = __expf(sc[j][0] * scale);
            float p1 = __expf(sc[j][1] * scale);
            float p2 = __expf(sc[j][2] * scale);
            float p3 = __expf(sc[j][3] * scale);
            l0 += p0 + p1; l1 += p2 + p3;
            sc[j][0] = p0; sc[j][1] = p1; sc[j][2] = p2; sc[j][3] = p3;
        }

        // O += P V (P split in registers, V split in smem; 3 terms)
        #pragma unroll
        for (int ks = 0; ks < 4; ks++) {
            uint32_t pa0, pa1, pa2, pa3, pb0, pb1, pb2, pb3;
            fsplit2(sc[2*ks][0],   sc[2*ks][1],   pa0, pb0);
            fsplit2(sc[2*ks][2],   sc[2*ks][3],   pa1, pb1);
            fsplit2(sc[2*ks+1][0], sc[2*ks+1][1], pa2, pb2);
            fsplit2(sc[2*ks+1][2], sc[2*ks+1][3], pa3, pb3);
            #pragma unroll
            for (int t = 0; t < 4; t++) {
                const uint32_t toff = t * (16 * ASTR * 2) + ks * 32;
                uint32_t bh0, bh1, bh2, bh3, bl0, bl1, bl2, bl3;
                LDSM_X4(bh0, bh1, bh2, bh3, vh_a + toff);
                LDSM_X4(bl0, bl1, bl2, bl3, vl_a + toff);
                mma16816s(o[2*t],   pa0, pa1, pa2, pa3, bh0, bh1);
                mma16816s(o[2*t],   pa0, pa1, pa2, pa3, bl0, bl1);
                mma16816s(o[2*t],   pb0, pb1, pb2, pb3, bh0, bh1);
                mma16816s(o[2*t+1], pa0, pa1, pa2, pa3, bh2, bh3);
                mma16816s(o[2*t+1], pa0, pa1, pa2, pa3, bl2, bl3);
                mma16816s(o[2*t+1], pb0, pb1, pb2, pb3, bh2, bh3);
            }
        }
    }

    // reduce l across the 4 tg lanes (once)
    #pragma unroll
    for (int off = 1; off <= 2; off <<= 1) {
        l0 += __shfl_xor_sync(0xffffffffu, l0, off);
        l1 += __shfl_xor_sync(0xffffffffu, l1, off);
    }

    // ---------------- half merge (addition), write z-partials ----------------
    __syncthreads();
    float* buf = (float*)asmem;     // reuse: [4][32][36]
    if (half) {
        float* p = buf + ((size_t)qw * 32 + lane) * 36;
        #pragma unroll
        for (int j = 0; j < 8; j++) {
            p[j * 4 + 0] = o[j][0]; p[j * 4 + 1] = o[j][1];
            p[j * 4 + 2] = o[j][2]; p[j * 4 + 3] = o[j][3];
        }
        p[32] = l0; p[33] = l1;
    }
    __syncthreads();
    if (!half) {
        const float* p = buf + ((size_t)qw * 32 + lane) * 36;
        const size_t row0r = (size_t)b * SEQ + q0 + wrow + g;
        const size_t row1r = row0r + 8;
        float* po = g_pO + (size_t)z * (BATCH * SEQ * DK);
        #pragma unroll
        for (int j = 0; j < 8; j++) {
            const int col = j * 8 + tg * 2;
            float o0 = o[j][0] + p[j * 4 + 0];
            float o1 = o[j][1] + p[j * 4 + 1];
            float o2 = o[j][2] + p[j * 4 + 2];
            float o3 = o[j][3] + p[j * 4 + 3];
            *(float2*)(po + row0r * DK + col) = make_float2(o0, o1);
            *(float2*)(po + row1r * DK + col) = make_float2(o2, o3);
        }
        if (tg == 0) {
            g_pl[(size_t)z * (BATCH * SEQ) + row0r] = l0 + p[32];
            g_pl[(size_t)z * (BATCH * SEQ) + row1r] = l1 + p[33];
        }
    }
}

// ============================ kv-split merge ============================
// out[row][col] = (O0+O1)/(l0+l1). 131072 threads, 4 floats each.
__global__ __launch_bounds__(256) void attn_merge(float* __restrict__ out)
{
    const int idx = blockIdx.x * 256 + threadIdx.x;
    const int row = idx >> 4;
    const int cg  = (idx & 15) * 4;
    const float inv = 1.0f / (g_pl[row] + g_pl[BATCH * SEQ + row]);
    const float* pa = g_pO + (size_t)row * DK + cg;
    const float* pb = pa + (size_t)BATCH * SEQ * DK;
    float4 a = *(const float4*)pa;
    float4 b = *(const float4*)pb;
    float4 r;
    r.x = (a.x + b.x) * inv; r.y = (a.y + b.y) * inv;
    r.z = (a.z + b.z) * inv; r.w = (a.w + b.w) * inv;
    *(float4*)(out + (size_t)row * DK + cg) = r;
}

// ============================ launch ============================
extern "C" void kernel_launch(void* const* d_in, const int* in_sizes, int n_in,
                              void* d_out, int out_size)
{
    const float* query = (const float*)d_in[0];
    const float* key   = (const float*)d_in[1];
    const float* value = (const float*)d_in[2];
    const float* Wq    = (const float*)d_in[3];
    const float* bq    = (const float*)d_in[4];
    const float* Wk    = (const float*)d_in[5];
    const float* bk    = (const float*)d_in[6];
    const float* Wv    = (const float*)d_in[7];
    const float* bv    = (const float*)d_in[8];
    float* out = (float*)d_out;

    static bool attr_set = false;
    if (!attr_set) {
        cudaFuncSetAttribute(proj_mma,
                             cudaFuncAttributeMaxDynamicSharedMemorySize, PROJ_SMEM);
        cudaFuncSetAttribute(attn_mma,
                             cudaFuncAttributeMaxDynamicSharedMemorySize, AT_BYTES);
        attr_set = true;
    }

    prep_w<<<dim3(3, 64), 256>>>(Wq, Wk, Wv);
    proj_mma<<<dim3(64, 3), 256, PROJ_SMEM>>>(query, key, value, bq, bk, bv);
    attn_mma<<<dim3(SEQ / 64, BATCH, 2), 256, AT_BYTES>>>();
    attn_merge<<<BATCH * SEQ * DK / (4 * 256), 256>>>(out);
}

// round 15
// speedup vs baseline: 1.0674x; 1.0674x over previous
#include <cuda_runtime.h>
#include <cuda_bf16.h>
#include <cstdint>
#include <math.h>

#define BATCH  4
#define SEQ    2048
#define DMODEL 1024
#define DK     64

// projected activations: Q, K single rn-bf16 (scores tolerate rn noise)
__device__ __align__(16) __nv_bfloat16 g_qh[BATCH * SEQ * DK];
__device__ __align__(16) __nv_bfloat16 g_kh[BATCH * SEQ * DK];
// V transposed: [batch][vcol][seq], split (V noise does NOT average out)
__device__ __align__(16) __nv_bfloat16 g_vth[BATCH * DK * SEQ];
__device__ __align__(16) __nv_bfloat16 g_vtl[BATCH * DK * SEQ];
// pre-transposed + bf16-split weights: [matrix][n][k]
__device__ __align__(16) __nv_bfloat16 g_wt_hi[3 * DK * DMODEL];
__device__ __align__(16) __nv_bfloat16 g_wt_lo[3 * DK * DMODEL];

// ============================ PTX helpers ============================
__device__ __forceinline__ uint32_t smem_u32(const void* p) {
    uint32_t a;
    asm("{ .reg .u64 t; cvta.to.shared.u64 t, %1; cvt.u32.u64 %0, t; }"
        : "=r"(a) : "l"(p));
    return a;
}
__device__ __forceinline__ void mma16816s(float c[4], uint32_t a0, uint32_t a1,
                                          uint32_t a2, uint32_t a3,
                                          uint32_t b0, uint32_t b1) {
    asm volatile(
        "mma.sync.aligned.m16n8k16.row.col.f32.bf16.bf16.f32 "
        "{%0, %1, %2, %3}, {%4, %5, %6, %7}, {%8, %9}, {%0, %1, %2, %3};"
        : "+f"(c[0]), "+f"(c[1]), "+f"(c[2]), "+f"(c[3])
        : "r"(a0), "r"(a1), "r"(a2), "r"(a3), "r"(b0), "r"(b1));
}
#define LDSM_X4(r0, r1, r2, r3, addr) \
    asm volatile("ldmatrix.sync.aligned.m8n8.x4.shared.b16 {%0,%1,%2,%3}, [%4];" \
        : "=r"(r0), "=r"(r1), "=r"(r2), "=r"(r3) : "r"(addr))
#define CP_ASYNC16(dst, src) \
    asm volatile("cp.async.cg.shared.global [%0], [%1], 16;" \
        :: "r"(dst), "l"(src) : "memory")
#define CP_COMMIT() asm volatile("cp.async.commit_group;" ::: "memory")
#define CP_WAIT0()  asm volatile("cp.async.wait_group 0;" ::: "memory")
#define CP_WAIT1()  asm volatile("cp.async.wait_group 1;" ::: "memory")

// Fast Dekker split: hi = truncate-to-bf16 (exact residual), lo = rn(residual).
__device__ __forceinline__ void fsplit2(float a, float b, uint32_t& hi, uint32_t& lo) {
    uint32_t ua = __float_as_uint(a), ub = __float_as_uint(b);
    hi = __byte_perm(ua, ub, 0x7632);
    float ra = a - __uint_as_float(ua & 0xffff0000u);
    float rb = b - __uint_as_float(ub & 0xffff0000u);
    __nv_bfloat162 l2 = __floats2bfloat162_rn(ra, rb);
    lo = *reinterpret_cast<uint32_t*>(&l2);
}
// round-to-nearest bf16x2 pack
__device__ __forceinline__ uint32_t frn2(float a, float b) {
    __nv_bfloat162 r2 = __floats2bfloat162_rn(a, b);
    return *reinterpret_cast<uint32_t*>(&r2);
}

// ============================ prep: transpose + split weights ============================
__global__ __launch_bounds__(256) void prep_w(const float* __restrict__ Wq,
                                              const float* __restrict__ Wk,
                                              const float* __restrict__ Wv)
{
    const int m = blockIdx.x;
    const float* W = (m == 0) ? Wq : (m == 1) ? Wk : Wv;   // [1024, 64] row-major
    __nv_bfloat16* th = g_wt_hi + m * DK * DMODEL;
    __nv_bfloat16* tl = g_wt_lo + m * DK * DMODEL;
    const int tid = threadIdx.x;
    const int k0 = blockIdx.y * 16;
    const int n = tid >> 2, kq = tid & 3;

    float v[4];
    #pragma unroll
    for (int e = 0; e < 4; e++)
        v[e] = __ldg(W + (size_t)(k0 + kq * 4 + e) * 64 + n);

    uint32_t h[2], l[2];
    #pragma unroll
    for (int e = 0; e < 2; e++) {
        float a = v[2 * e], b = v[2 * e + 1];
        uint32_t ua = __float_as_uint(a), ub = __float_as_uint(b);
        h[e] = __byte_perm(ua, ub, 0x7632);
        float ra = a - __uint_as_float(ua & 0xffff0000u);
        float rb = b - __uint_as_float(ub & 0xffff0000u);
        l[e] = frn2(ra, rb);
    }
    size_t off = (size_t)n * DMODEL + k0 + kq * 4;
    *(uint2*)&th[off] = make_uint2(h[0], h[1]);
    *(uint2*)&tl[off] = make_uint2(l[0], l[1]);
}

// ============================ mma.sync projection ============================
// X loaded directly as register A-fragments; W 3-buffer cp.async pipeline.
#define WSTR 72
static const int WBUF_E = 2 * 64 * WSTR;           // hi+lo per buffer = 9216 elems
static const int WBUF_B = WBUF_E * 2;              // 18432 B
static const int PROJ_SMEM = 3 * WBUF_B;           // 55296 B (>= V stage 33792 B)

__global__ __launch_bounds__(256, 2) void proj_mma(
    const float* __restrict__ Xq, const float* __restrict__ Xk,
    const float* __restrict__ Xv,
    const float* __restrict__ bq, const float* __restrict__ bk,
    const float* __restrict__ bv)
{
    extern __shared__ __nv_bfloat16 sm[];

    const int tid = threadIdx.x;
    const int wid = tid >> 5;
    const int lane = tid & 31;
    const int g  = lane >> 2;
    const int tg = lane & 3;
    const int m = blockIdx.y;
    const int row0 = blockIdx.x * 128;
    const int wrow = wid * 16;

    const float* X    = (m == 0) ? Xq : (m == 1) ? Xk : Xv;
    const float* bias = (m == 0) ? bq : (m == 1) ? bk : bv;
    const __nv_bfloat16* wh = g_wt_hi + m * DK * DMODEL;
    const __nv_bfloat16* wl = g_wt_lo + m * DK * DMODEL;

    float acc[8][4];
    #pragma unroll
    for (int j = 0; j < 8; j++)
        #pragma unroll
        for (int q = 0; q < 4; q++) acc[j][q] = 0.0f;

    const uint32_t sb = smem_u32(sm);

    const int wn0 = tid >> 3, wc0 = (tid & 7) * 8;
    const int wn1 = (tid + 256) >> 3, wc1 = ((tid + 256) & 7) * 8;
    const uint32_t wd0 = (uint32_t)((wn0 * WSTR + wc0) * 2);
    const uint32_t wd1 = (uint32_t)((wn1 * WSTR + wc1) * 2);
    const uint32_t wlofs = (uint32_t)(64 * WSTR * 2);

    const int brow = (lane & 7) + ((lane >> 4) & 1) * 8;
    const uint32_t wlm = (uint32_t)((brow * WSTR + ((lane >> 3) & 1) * 8) * 2);

    const float* xb = X + (size_t)(row0 + wrow + g) * DMODEL + tg * 2;

    float2 xf[4][4];
    #pragma unroll
    for (int ks = 0; ks < 4; ks++) {
        const float* p = xb + ks * 16;
        xf[ks][0] = *(const float2*)(p);
        xf[ks][1] = *(const float2*)(p + 8 * DMODEL);
        xf[ks][2] = *(const float2*)(p + 8);
        xf[ks][3] = *(const float2*)(p + 8 * DMODEL + 8);
    }

    auto stage_w = [&](int b, int c) {
        const uint32_t base = sb + (uint32_t)(b * WBUF_B);
        const int co = c * 64;
        CP_ASYNC16(base + wd0,         wh + wn0 * DMODEL + co + wc0);
        CP_ASYNC16(base + wd0 + wlofs, wl + wn0 * DMODEL + co + wc0);
        CP_ASYNC16(base + wd1,         wh + wn1 * DMODEL + co + wc1);
        CP_ASYNC16(base + wd1 + wlofs, wl + wn1 * DMODEL + co + wc1);
        CP_COMMIT();
    };
    stage_w(0, 0);
    stage_w(1, 1);

    for (int c = 0; c < 16; c++) {
        if (c < 15) { CP_WAIT1(); } else { CP_WAIT0(); }
        __syncthreads();
        if (c < 14) stage_w((c + 2) % 3, c + 2);

        const uint32_t whb = sb + (uint32_t)((c % 3) * WBUF_B) + wlm;
        const uint32_t wlb = whb + wlofs;

        #pragma unroll
        for (int ks = 0; ks < 4; ks++) {
            uint32_t ah0, ah1, ah2, ah3, al0, al1, al2, al3;
            fsplit2(xf[ks][0].x, xf[ks][0].y, ah0, al0);
            fsplit2(xf[ks][1].x, xf[ks][1].y, ah1, al1);
            fsplit2(xf[ks][2].x, xf[ks][2].y, ah2, al2);
            fsplit2(xf[ks][3].x, xf[ks][3].y, ah3, al3);
            #pragma unroll
            for (int t = 0; t < 4; t++) {
                const uint32_t toff = t * (16 * WSTR * 2) + ks * 32;
                uint32_t bh0, bh1, bh2, bh3, bl0, bl1, bl2, bl3;
                LDSM_X4(bh0, bh1, bh2, bh3, whb + toff);
                LDSM_X4(bl0, bl1, bl2, bl3, wlb + toff);
                mma16816s(acc[2*t],   ah0, ah1, ah2, ah3, bh0, bh1);
                mma16816s(acc[2*t],   ah0, ah1, ah2, ah3, bl0, bl1);
                mma16816s(acc[2*t],   al0, al1, al2, al3, bh0, bh1);
                mma16816s(acc[2*t+1], ah0, ah1, ah2, ah3, bh2, bh3);
                mma16816s(acc[2*t+1], ah0, ah1, ah2, ah3, bl2, bl3);
                mma16816s(acc[2*t+1], al0, al1, al2, al3, bh2, bh3);
            }
        }

        if (c < 15) {
            const float* xc = xb + (c + 1) * 64;
            #pragma unroll
            for (int ks = 0; ks < 4; ks++) {
                const float* p = xc + ks * 16;
                xf[ks][0] = *(const float2*)(p);
                xf[ks][1] = *(const float2*)(p + 8 * DMODEL);
                xf[ks][2] = *(const float2*)(p + 8);
                xf[ks][3] = *(const float2*)(p + 8 * DMODEL + 8);
            }
        }
    }

    // ---------------- epilogue ----------------
    if (m < 2) {
        // Q, K: +bias, single rn-bf16 (unbiased; score noise averages per model)
        __nv_bfloat16* outh = (m == 0) ? g_qh : g_kh;
        #pragma unroll
        for (int j = 0; j < 8; j++) {
            const int col = j * 8 + tg * 2;
            const float b0 = __ldg(bias + col);
            const float b1 = __ldg(bias + col + 1);
            size_t r0 = (size_t)(row0 + wrow + g) * DK + col;
            size_t r1 = (size_t)(row0 + wrow + g + 8) * DK + col;
            *(uint32_t*)&outh[r0] = frn2(acc[j][0] + b0, acc[j][1] + b1);
            *(uint32_t*)&outh[r1] = frn2(acc[j][2] + b0, acc[j][3] + b1);
        }
    } else {
        // V: stage fp32 in smem, then transposed split-bf16 store
        __syncthreads();
        float* stage = (float*)sm;    // [128][66] = 33792 B
        #pragma unroll
        for (int j = 0; j < 8; j++) {
            const int col = j * 8 + tg * 2;
            const float b0 = __ldg(bias + col);
            const float b1 = __ldg(bias + col + 1);
            stage[(wrow + g) * 66 + col]         = acc[j][0] + b0;
            stage[(wrow + g) * 66 + col + 1]     = acc[j][1] + b1;
            stage[(wrow + g + 8) * 66 + col]     = acc[j][2] + b0;
            stage[(wrow + g + 8) * 66 + col + 1] = acc[j][3] + b1;
        }
        __syncthreads();
        const int bb   = row0 >> 11;
        const int srow = row0 & 2047;
        const int vc = tid >> 2;
        #pragma unroll
        for (int i = 0; i < 16; i++) {
            int sp = (tid & 3) + i * 4;
            int s0 = sp * 2;
            uint32_t h, l;
            fsplit2(stage[s0 * 66 + vc], stage[(s0 + 1) * 66 + vc], h, l);
            size_t off = ((size_t)bb * DK + vc) * SEQ + srow + s0;
            *(uint32_t*)&g_vth[off] = h;
            *(uint32_t*)&g_vtl[off] = l;
        }
    }
}

// ============================ mma.sync flash attention ============================
// grid (32, 4): 64 queries/CTA, 8 warps (0-3 even key tiles, 4-7 odd).
// Q, K single rn-bf16 (QK = 1 MMA term); V split (PV 3 terms).
// cp.async double-buffered; in-kernel half merge; direct output.
#define ASTR 72
static const int TILE_E = 64 * ASTR;                 // 4608 elems per tile
static const int ABUF_E = 6 * TILE_E;                // 2 tiles x 3 arrays
static const int AT_BYTES = 2 * ABUF_E * 2;          // 110592 B

__device__ __forceinline__ void attn_stage(int b, int it, int buf, uint32_t sb, int tid)
{
    const uint32_t bufb = (uint32_t)(buf * ABUF_E * 2);
    #pragma unroll
    for (int t = 0; t < 2; t++) {
        const int kb = it * 2 + t;
        #pragma unroll
        for (int u = 0; u < 2; u++) {
            int idx = tid + u * 256;
            int r = idx >> 3, cq = idx & 7;
            size_t koff = ((size_t)b * SEQ + kb * 64 + r) * DK + cq * 8;
            size_t voff = ((size_t)b * DK + r) * SEQ + kb * 64 + cq * 8;
            uint32_t dst = sb + bufb + (uint32_t)((t * TILE_E + r * ASTR + cq * 8) * 2);
            CP_ASYNC16(dst,                  g_kh + koff);
            CP_ASYNC16(dst + 2 * TILE_E * 2, g_vth + voff);
            CP_ASYNC16(dst + 4 * TILE_E * 2, g_vtl + voff);
        }
    }
}

__global__ __launch_bounds__(256) void attn_mma(float* __restrict__ out)
{
    extern __shared__ __nv_bfloat16 asmem[];

    const int b  = blockIdx.y;
    const int q0 = blockIdx.x * 64;
    const int tid = threadIdx.x;
    const int wid = tid >> 5;
    const int lane = tid & 31;
    const int g  = lane >> 2;
    const int tg = lane & 3;
    const int qw = wid & 3;          // query slab
    const int half = wid >> 2;       // key-half
    const int wrow = qw * 16;
    const float scale = 0.125f;

    const uint32_t sb = smem_u32(asmem);
    const int brow = (lane & 7) + ((lane >> 4) & 1) * 8;
    const uint32_t lmo = (uint32_t)((brow * ASTR + ((lane >> 3) & 1) * 8) * 2);

    // Q fragments (single rn-bf16)
    const size_t qbase = (size_t)b * SEQ + q0 + wrow;
    uint32_t qh[4][4];
    #pragma unroll
    for (int ks = 0; ks < 4; ks++) {
        const int c0 = ks * 16 + tg * 2;
        qh[ks][0] = *(const uint32_t*)&g_qh[(qbase + g    ) * DK + c0];
        qh[ks][1] = *(const uint32_t*)&g_qh[(qbase + g + 8) * DK + c0];
        qh[ks][2] = *(const uint32_t*)&g_qh[(qbase + g    ) * DK + c0 + 8];
        qh[ks][3] = *(const uint32_t*)&g_qh[(qbase + g + 8) * DK + c0 + 8];
    }

    float l0 = 0.0f, l1 = 0.0f;
    float o[8][4];
    #pragma unroll
    for (int j = 0; j < 8; j++)
        #pragma unroll
        for (int q = 0; q < 4; q++) o[j][q] = 0.0f;

    attn_stage(b, 0, 0, sb, tid);
    CP_COMMIT();

    for (int it = 0; it < 16; it++) {
        const int bf = it & 1;
        CP_WAIT0();
        __syncthreads();
        if (it < 15) {
            attn_stage(b, it + 1, bf ^ 1, sb, tid);
            CP_COMMIT();
        }

        const uint32_t kh_a = sb + (uint32_t)(bf * ABUF_E * 2) +
                              (uint32_t)(half * TILE_E * 2) + lmo;
        const uint32_t vh_a = kh_a + 2 * TILE_E * 2;
        const uint32_t vl_a = kh_a + 4 * TILE_E * 2;

        // S = Q K^T (single term)
        float sc[8][4];
        #pragma unroll
        for (int j = 0; j < 8; j++)
            #pragma unroll
            for (int q = 0; q < 4; q++) sc[j][q] = 0.0f;
        #pragma unroll
        for (int ks = 0; ks < 4; ks++) {
            #pragma unroll
            for (int t = 0; t < 4; t++) {
                const uint32_t toff = t * (16 * ASTR * 2) + ks * 32;
                uint32_t bh0, bh1, bh2, bh3;
                LDSM_X4(bh0, bh1, bh2, bh3, kh_a + toff);
                mma16816s(sc[2*t],   qh[ks][0], qh[ks][1], qh[ks][2], qh[ks][3], bh0, bh1);
                mma16816s(sc[2*t+1], qh[ks][0], qh[ks][1], qh[ks][2], qh[ks][3], bh2, bh3);
            }
        }

        // p = exp(s*scale); accumulate l per-lane
        #pragma unroll
        for (int j = 0; j < 8; j++) {
            float p0 = __expf(sc[j][0] * scale);
            float p1 = __expf(sc[j][1] * scale);
            float p2 = __expf(sc[j][2] * scale);
            float p3 = __expf(sc[j][3] * scale);
            l0 += p0 + p1; l1 += p2 + p3;
            sc[j][0] = p0; sc[j][1] = p1; sc[j][2] = p2; sc[j][3] = p3;
        }

        // O += P V (P split in registers, V split in smem; 3 terms)
        #pragma unroll
        for (int ks = 0; ks < 4; ks++) {
            uint32_t pa0, pa1, pa2, pa3, pb0, pb1, pb2, pb3;
            fsplit2(sc[2*ks][0],   sc[2*ks][1],   pa0, pb0);
            fsplit2(sc[2*ks][2],   sc[2*ks][3],   pa1, pb1);
            fsplit2(sc[2*ks+1][0], sc[2*ks+1][1], pa2, pb2);
            fsplit2(sc[2*ks+1][2], sc[2*ks+1][3], pa3, pb3);
            #pragma unroll
            for (int t = 0; t < 4; t++) {
                const uint32_t toff = t * (16 * ASTR * 2) + ks * 32;
                uint32_t bh0, bh1, bh2, bh3, bl0, bl1, bl2, bl3;
                LDSM_X4(bh0, bh1, bh2, bh3, vh_a + toff);
                LDSM_X4(bl0, bl1, bl2, bl3, vl_a + toff);
                mma16816s(o[2*t],   pa0, pa1, pa2, pa3, bh0, bh1);
                mma16816s(o[2*t],   pa0, pa1, pa2, pa3, bl0, bl1);
                mma16816s(o[2*t],   pb0, pb1, pb2, pb3, bh0, bh1);
                mma16816s(o[2*t+1], pa0, pa1, pa2, pa3, bh2, bh3);
                mma16816s(o[2*t+1], pa0, pa1, pa2, pa3, bl2, bl3);
                mma16816s(o[2*t+1], pb0, pb1, pb2, pb3, bh2, bh3);
            }
        }
    }

    // reduce l across the 4 tg lanes (once)
    #pragma unroll
    for (int off = 1; off <= 2; off <<= 1) {
        l0 += __shfl_xor_sync(0xffffffffu, l0, off);
        l1 += __shfl_xor_sync(0xffffffffu, l1, off);
    }

    // ---------------- half merge: plain addition ----------------
    __syncthreads();
    float* buf = (float*)asmem;     // reuse: [4][32][36]
    if (half) {
        float* p = buf + ((size_t)qw * 32 + lane) * 36;
        #pragma unroll
        for (int j = 0; j < 8; j++) {
            p[j * 4 + 0] = o[j][0]; p[j * 4 + 1] = o[j][1];
            p[j * 4 + 2] = o[j][2]; p[j * 4 + 3] = o[j][3];
        }
        p[32] = l0; p[33] = l1;
    }
    __syncthreads();
    if (!half) {
        const float* p = buf + ((size_t)qw * 32 + lane) * 36;
        const float inv0 = 1.0f / (l0 + p[32]);
        const float inv1 = 1.0f / (l1 + p[33]);
        #pragma unroll
        for (int j = 0; j < 8; j++) {
            const int col = j * 8 + tg * 2;
            size_t r0 = ((size_t)b * SEQ + q0 + wrow + g    ) * DK + col;
            size_t r1 = ((size_t)b * SEQ + q0 + wrow + g + 8) * DK + col;
            float o0 = (o[j][0] + p[j * 4 + 0]) * inv0;
            float o1 = (o[j][1] + p[j * 4 + 1]) * inv0;
            float o2 = (o[j][2] + p[j * 4 + 2]) * inv1;
            float o3 = (o[j][3] + p[j * 4 + 3]) * inv1;
            *(float2*)(out + r0) = make_float2(o0, o1);
            *(float2*)(out + r1) = make_float2(o2, o3);
        }
    }
}

// ============================ launch ============================
extern "C" void kernel_launch(void* const* d_in, const int* in_sizes, int n_in,
                              void* d_out, int out_size)
{
    const float* query = (const float*)d_in[0];
    const float* key   = (const float*)d_in[1];
    const float* value = (const float*)d_in[2];
    const float* Wq    = (const float*)d_in[3];
    const float* bq    = (const float*)d_in[4];
    const float* Wk    = (const float*)d_in[5];
    const float* bk    = (const float*)d_in[6];
    const float* Wv    = (const float*)d_in[7];
    const float* bv    = (const float*)d_in[8];
    float* out = (float*)d_out;

    static bool attr_set = false;
    if (!attr_set) {
        cudaFuncSetAttribute(proj_mma,
                             cudaFuncAttributeMaxDynamicSharedMemorySize, PROJ_SMEM);
        cudaFuncSetAttribute(attn_mma,
                             cudaFuncAttributeMaxDynamicSharedMemorySize, AT_BYTES);
        attr_set = true;
    }

    prep_w<<<dim3(3, 64), 256>>>(Wq, Wk, Wv);
    proj_mma<<<dim3(64, 3), 256, PROJ_SMEM>>>(query, key, value, bq, bk, bv);
    attn_mma<<<dim3(SEQ / 64, BATCH), 256, AT_BYTES>>>(out);
}